// round 1
// baseline (speedup 1.0000x reference)
#include <cuda_runtime.h>
#include <math.h>

#define D_MODEL 1024
#define NHEADS  16
#define HD      64
#define NB      4
#define CTX     2048
#define EDIM    (3 * D_MODEL)
#define TOK     (NB * CTX)

// scratch for z = x @ W^T + b : [TOK, 3*D]  (96 MB, static per allocation rules)
__device__ float g_z[(size_t)TOK * EDIM];

// ---------------------------------------------------------------------------
// Kernel 1: z[t,e] = sum_k x[t,k] * W[e,k] + b[e]
// Classic 128x128x8 register-blocked SGEMM (8x8 micro-tile per thread).
// ---------------------------------------------------------------------------
__global__ __launch_bounds__(256) void qkv_gemm(const float* __restrict__ x,
                                                const float* __restrict__ W,
                                                const float* __restrict__ b) {
    const int BM = 128, BN = 128, BK = 8;
    __shared__ float As[BK][BM];
    __shared__ float Bs[BK][BN];

    const int tid = threadIdx.x;
    const int tx = tid & 15;        // 0..15  (N direction)
    const int ty = tid >> 4;        // 0..15  (M direction)
    const int t0 = blockIdx.y * BM; // token block
    const int e0 = blockIdx.x * BN; // output-feature block

    // cooperative load mapping: 128 rows x 8 k -> 256 float4 loads (1 per thread)
    const int lrow  = tid >> 1;       // 0..127
    const int lcol4 = (tid & 1) * 4;  // 0 or 4

    float acc[8][8];
#pragma unroll
    for (int m = 0; m < 8; m++)
#pragma unroll
        for (int n = 0; n < 8; n++) acc[m][n] = 0.f;

    for (int k0 = 0; k0 < D_MODEL; k0 += BK) {
        float4 av = *(const float4*)&x[(size_t)(t0 + lrow) * D_MODEL + k0 + lcol4];
        float4 bv = *(const float4*)&W[(size_t)(e0 + lrow) * D_MODEL + k0 + lcol4];
        As[lcol4 + 0][lrow] = av.x;
        As[lcol4 + 1][lrow] = av.y;
        As[lcol4 + 2][lrow] = av.z;
        As[lcol4 + 3][lrow] = av.w;
        Bs[lcol4 + 0][lrow] = bv.x;
        Bs[lcol4 + 1][lrow] = bv.y;
        Bs[lcol4 + 2][lrow] = bv.z;
        Bs[lcol4 + 3][lrow] = bv.w;
        __syncthreads();

#pragma unroll
        for (int k = 0; k < BK; k++) {
            float ra[8], rb[8];
            *(float4*)&ra[0] = *(const float4*)&As[k][ty * 8];
            *(float4*)&ra[4] = *(const float4*)&As[k][ty * 8 + 4];
            *(float4*)&rb[0] = *(const float4*)&Bs[k][tx * 8];
            *(float4*)&rb[4] = *(const float4*)&Bs[k][tx * 8 + 4];
#pragma unroll
            for (int m = 0; m < 8; m++)
#pragma unroll
                for (int n = 0; n < 8; n++) acc[m][n] += ra[m] * rb[n];
        }
        __syncthreads();
    }

#pragma unroll
    for (int m = 0; m < 8; m++) {
        const size_t t = (size_t)(t0 + ty * 8 + m);
#pragma unroll
        for (int n = 0; n < 8; n += 4) {
            const int e = e0 + tx * 8 + n;
            float4 bb = *(const float4*)&b[e];
            float4 w;
            w.x = acc[m][n + 0] + bb.x;
            w.y = acc[m][n + 1] + bb.y;
            w.z = acc[m][n + 2] + bb.z;
            w.w = acc[m][n + 3] + bb.w;
            *(float4*)&g_z[t * EDIM + e] = w;
        }
    }
}

// ---------------------------------------------------------------------------
// Kernel 2: causal attention, flash style.
// Block = 128 threads = 128 query rows of one (n, h). K/V tiles of 64 rows in
// SMEM, online softmax with lazy rescale, q pre-scaled by D^-1/2.
// z layout: k at [0,D), q at [D,2D), v at [2D,3D); head h owns dims h*64..+64.
// ---------------------------------------------------------------------------
__global__ __launch_bounds__(128) void attn_kernel(float* __restrict__ out) {
    __shared__ float Ks[64][HD];
    __shared__ float Vs[64][HD];

    const int qb  = blockIdx.x;   // query block (128 rows)
    const int h   = blockIdx.y;
    const int n   = blockIdx.z;
    const int tid = threadIdx.x;
    const int i   = qb * 128 + tid;  // this thread's query row

    const float scale = 1.0f / 32.0f;  // D_MODEL^-0.5, exact

    float q[HD], o[HD];
    {
        const float* zq = &g_z[((size_t)(n * CTX + i)) * EDIM + D_MODEL + h * HD];
#pragma unroll
        for (int d4 = 0; d4 < 16; d4++) {
            float4 v = *(const float4*)&zq[d4 * 4];
            q[d4 * 4 + 0] = v.x * scale;
            q[d4 * 4 + 1] = v.y * scale;
            q[d4 * 4 + 2] = v.z * scale;
            q[d4 * 4 + 3] = v.w * scale;
        }
    }
#pragma unroll
    for (int d = 0; d < HD; d++) o[d] = 0.f;
    float m = -1e30f, l = 0.f;

    const int ntiles = qb * 2 + 2;  // key tiles covering keys <= qb*128+127
    for (int jt = 0; jt < ntiles; jt++) {
        __syncthreads();  // protect smem from previous iteration's readers
        {
            const float* zk = &g_z[((size_t)(n * CTX + jt * 64)) * EDIM + h * HD];
            const float* zv = zk + 2 * D_MODEL;
#pragma unroll
            for (int s = tid; s < 1024; s += 128) {
                const int r = s >> 4, c4 = (s & 15) * 4;
                *(float4*)&Ks[r][c4] = *(const float4*)&zk[(size_t)r * EDIM + c4];
                *(float4*)&Vs[r][c4] = *(const float4*)&zv[(size_t)r * EDIM + c4];
            }
        }
        __syncthreads();

        const int lim = min(64, i - jt * 64 + 1);
        for (int jj = 0; jj < lim; jj++) {
            float s = 0.f;
            const float4* k4 = (const float4*)Ks[jj];
#pragma unroll
            for (int d4 = 0; d4 < 16; d4++) {
                float4 kv = k4[d4];
                s += q[d4 * 4 + 0] * kv.x;
                s += q[d4 * 4 + 1] * kv.y;
                s += q[d4 * 4 + 2] * kv.z;
                s += q[d4 * 4 + 3] * kv.w;
            }
            if (s > m) {  // lazy rescale (rare)
                const float corr = __expf(m - s);
                m = s;
                l *= corr;
#pragma unroll
                for (int d = 0; d < HD; d++) o[d] *= corr;
            }
            const float p = __expf(s - m);
            l += p;
            const float4* v4 = (const float4*)Vs[jj];
#pragma unroll
            for (int d4 = 0; d4 < 16; d4++) {
                float4 vv = v4[d4];
                o[d4 * 4 + 0] += p * vv.x;
                o[d4 * 4 + 1] += p * vv.y;
                o[d4 * 4 + 2] += p * vv.z;
                o[d4 * 4 + 3] += p * vv.w;
            }
        }
    }

    const float inv = 1.f / l;
    float* op = &out[((size_t)(n * CTX + i)) * D_MODEL + h * HD];
#pragma unroll
    for (int d4 = 0; d4 < 16; d4++) {
        float4 w;
        w.x = o[d4 * 4 + 0] * inv;
        w.y = o[d4 * 4 + 1] * inv;
        w.z = o[d4 * 4 + 2] * inv;
        w.w = o[d4 * 4 + 3] * inv;
        *(float4*)&op[d4 * 4] = w;
    }
}

extern "C" void kernel_launch(void* const* d_in, const int* in_sizes, int n_in,
                              void* d_out, int out_size) {
    const float* x = (const float*)d_in[0];
    const float* W = (const float*)d_in[1];
    const float* b = (const float*)d_in[2];
    float* out = (float*)d_out;

    dim3 g1(EDIM / 128, TOK / 128);   // 24 x 64
    qkv_gemm<<<g1, 256>>>(x, W, b);

    dim3 g2(CTX / 128, NHEADS, NB);   // 16 x 16 x 4
    attn_kernel<<<g2, 128>>>(out);
}